// round 4
// baseline (speedup 1.0000x reference)
#include <cuda_runtime.h>

#define HDIM 2880
#define NEXP 32
#define TOPK 4
#define TOK_TILE 64
#define HC 64            // H per stage -> 45 chunks
#define HPAD 68          // 68 mod 32 = 4 -> W rows hit distinct bank-quads: conflict-free LDS.128
#define NCHUNK (HDIM / HC)
#define NTHREADS 128     // 4 warps x 16 tokens
#define XF4 (TOK_TILE * HC / 4)   // 1024
#define WF4 (NEXP * HC / 4)       // 512

// Packed dual-fp32 FMA (PTX-only; ptxas never auto-fuses to FFMA2)
__device__ __forceinline__ void fma2(unsigned long long &acc,
                                     unsigned long long a,
                                     unsigned long long b) {
    asm("fma.rn.f32x2 %0, %1, %2, %3;" : "=l"(acc) : "l"(a), "l"(b), "l"(acc));
}

__device__ __forceinline__ void cp_async16(unsigned saddr, const void* gaddr) {
    asm volatile("cp.async.cg.shared.global [%0], [%1], 16;" :: "r"(saddr), "l"(gaddr));
}

__global__ __launch_bounds__(NTHREADS) void gate_kernel(
    const float* __restrict__ X,     // [T, H]
    const float* __restrict__ W,     // [E, H]
    const float* __restrict__ bias,  // [E]
    float* __restrict__ out,         // [T*K] idx-as-float, then [T*K] weights
    int T)
{
    __shared__ float xs[2][TOK_TILE][HPAD];
    __shared__ float ws[2][NEXP][HPAD];

    const int tid  = threadIdx.x;
    const int lane = tid & 31;       // lane == expert
    const int wid  = tid >> 5;
    const int t0   = blockIdx.x * TOK_TILE;
    const int wtok = wid * 16;       // this warp's first token within the tile

    // 16 tokens per lane-expert, packed {even-h, odd-h} fp32 accumulators
    unsigned long long acc[16];
    #pragma unroll
    for (int t = 0; t < 16; t++) acc[t] = 0ULL;

    auto load_chunk = [&](int c, int b) {
        const float* Xc = X + (size_t)t0 * HDIM + c * HC;
        const float* Wc = W + c * HC;
        #pragma unroll
        for (int it = 0; it < XF4 / NTHREADS; it++) {   // 8
            int idx = tid + it * NTHREADS;
            int row = idx >> 4, col = (idx & 15) * 4;
            unsigned s = (unsigned)__cvta_generic_to_shared(&xs[b][row][col]);
            cp_async16(s, Xc + (size_t)row * HDIM + col);
        }
        #pragma unroll
        for (int it = 0; it < WF4 / NTHREADS; it++) {   // 4
            int idx = tid + it * NTHREADS;
            int row = idx >> 4, col = (idx & 15) * 4;
            unsigned s = (unsigned)__cvta_generic_to_shared(&ws[b][row][col]);
            cp_async16(s, Wc + (size_t)row * HDIM + col);
        }
        asm volatile("cp.async.commit_group;");
    };

    load_chunk(0, 0);

    for (int c = 0; c < NCHUNK; c++) {
        const int b = c & 1;
        if (c + 1 < NCHUNK) {
            load_chunk(c + 1, b ^ 1);
            asm volatile("cp.async.wait_group 1;");
        } else {
            asm volatile("cp.async.wait_group 0;");
        }
        __syncthreads();

        const float* wrow = ws[b][lane];     // this lane's expert row
        #pragma unroll 4
        for (int q = 0; q < HC / 4; q++) {
            ulonglong2 wq = *(const ulonglong2*)(wrow + q * 4);   // 1 LDS.128, conflict-free
            #pragma unroll
            for (int t = 0; t < 16; t++) {
                // broadcast load: all lanes read the same 16B
                ulonglong2 xq = *(const ulonglong2*)(&xs[b][wtok + t][q * 4]);
                fma2(acc[t], xq.x, wq.x);
                fma2(acc[t], xq.y, wq.y);
            }
        }
        __syncthreads();
    }

    // ---- epilogue: per-token top-4 across lanes (lane == expert) ----
    const float bias_l = bias[lane];
    const int warp_t0 = t0 + wtok;

    #pragma unroll 2
    for (int t = 0; t < 16; t++) {
        float lo = __uint_as_float((unsigned)(acc[t] & 0xffffffffULL));
        float hi = __uint_as_float((unsigned)(acc[t] >> 32));
        float cur = lo + hi + bias_l;       // this lane's logit for token t

        float vals[TOPK];
        int   idxs[TOPK];
        #pragma unroll
        for (int k = 0; k < TOPK; k++) {
            float mv = cur;
            int   mi = lane;
            #pragma unroll
            for (int off = 16; off > 0; off >>= 1) {
                float ov = __shfl_xor_sync(0xffffffffu, mv, off);
                int   oi = __shfl_xor_sync(0xffffffffu, mi, off);
                // ties -> lower expert index (matches jax stable top_k)
                if (ov > mv || (ov == mv && oi < mi)) { mv = ov; mi = oi; }
            }
            vals[k] = mv;
            idxs[k] = mi;
            if (mi == lane) cur = -3.4e38f;  // remove winner from this lane
        }

        if (lane == 0) {
            float e0 = __expf(vals[0] - vals[0]);
            float e1 = __expf(vals[1] - vals[0]);
            float e2 = __expf(vals[2] - vals[0]);
            float e3 = __expf(vals[3] - vals[0]);
            float inv = 1.0f / (e0 + e1 + e2 + e3);
            size_t base = (size_t)(warp_t0 + t) * TOPK;
            float4 fi = make_float4((float)idxs[0], (float)idxs[1],
                                    (float)idxs[2], (float)idxs[3]);
            float4 fw = make_float4(e0 * inv, e1 * inv, e2 * inv, e3 * inv);
            *(float4*)&out[base] = fi;
            *(float4*)&out[(size_t)T * TOPK + base] = fw;
        }
    }
}

extern "C" void kernel_launch(void* const* d_in, const int* in_sizes, int n_in,
                              void* d_out, int out_size) {
    const float* X    = (const float*)d_in[0];
    const float* W    = (const float*)d_in[1];
    const float* bias = (const float*)d_in[2];
    int T = in_sizes[0] / HDIM;          // 16384
    int blocks = T / TOK_TILE;           // 256
    gate_kernel<<<blocks, NTHREADS>>>(X, W, bias, (float*)d_out, T);
}

// round 5
// speedup vs baseline: 2.0359x; 2.0359x over previous
#include <cuda_runtime.h>

#define HDIM 2880
#define NEXP 32
#define TOPK 4
#define TOK_TILE 64
#define HC 64                 // floats per chunk-row; 45 chunks
#define NCHUNK (HDIM / HC)    // 45
#define NQ 16                 // 16B-quads per row per chunk
#define NTHREADS 128

// Packed dual-fp32 FMA (PTX-only; ptxas never auto-fuses to FFMA2)
__device__ __forceinline__ void fma2(unsigned long long &acc,
                                     unsigned long long a,
                                     unsigned long long b) {
    asm("fma.rn.f32x2 %0, %1, %2, %3;" : "=l"(acc) : "l"(a), "l"(b), "l"(acc));
}
__device__ __forceinline__ void cp_async16(unsigned saddr, const void* gaddr) {
    asm volatile("cp.async.cg.shared.global [%0], [%1], 16;" :: "r"(saddr), "l"(gaddr));
}
__device__ __forceinline__ float accsum(unsigned long long a) {
    return __uint_as_float((unsigned)(a & 0xffffffffULL)) +
           __uint_as_float((unsigned)(a >> 32));
}

__global__ __launch_bounds__(NTHREADS) void gate_kernel(
    const float* __restrict__ X,     // [T, H]
    const float* __restrict__ W,     // [E, H]
    const float* __restrict__ bias,  // [E]
    float* __restrict__ out,         // [T*K] idx-as-float, then [T*K] weights
    int T)
{
    // [stage][row][col]: rows 0..63 = X tokens, rows 64..95 = W experts. 48KB.
    __shared__ float sm[2][96][HC];

    const int tid  = threadIdx.x;
    const int lane = tid & 31;
    const int wid  = tid >> 5;
    const int tt   = lane >> 2;   // token-thread 0..7  -> tokens tt*8..tt*8+7
    const int et   = lane & 3;    // expert-thread 0..3 -> experts et*8..et*8+7
    const int t0   = blockIdx.x * TOK_TILE;

    // 8 tokens x 8 experts packed {even,odd} fp32 accumulators = 128 regs
    unsigned long long acc[8][8];
    #pragma unroll
    for (int i = 0; i < 8; i++)
        #pragma unroll
        for (int j = 0; j < 8; j++) acc[i][j] = 0ULL;

    // stage chunk c into buffer b with XOR quad swizzle q' = q ^ (row>>3)
    auto load_chunk = [&](int c, int b) {
        const float* Xc = X + (size_t)t0 * HDIM + c * HC;
        const float* Wc = W + c * HC;
        #pragma unroll
        for (int it = 0; it < 8; it++) {           // 64 rows * 16 quads / 128 thr
            int idx = tid + it * NTHREADS;
            int row = idx >> 4, q = idx & 15;
            int dq = q ^ ((row >> 3) & 7);
            unsigned s = (unsigned)__cvta_generic_to_shared(&sm[b][row][dq * 4]);
            cp_async16(s, Xc + (size_t)row * HDIM + q * 4);
        }
        #pragma unroll
        for (int it = 0; it < 4; it++) {           // 32 rows * 16 quads / 128 thr
            int idx = tid + it * NTHREADS;
            int row = idx >> 4, q = idx & 15;
            int dq = q ^ ((row >> 3) & 3);
            unsigned s = (unsigned)__cvta_generic_to_shared(&sm[b][64 + row][dq * 4]);
            cp_async16(s, Wc + (size_t)row * HDIM + q * 4);
        }
        asm volatile("cp.async.commit_group;");
    };

    load_chunk(0, 0);

    for (int c = 0; c < NCHUNK; c++) {
        const int b = c & 1;
        if (c + 1 < NCHUNK) {
            load_chunk(c + 1, b ^ 1);
            asm volatile("cp.async.wait_group 1;");
        } else {
            asm volatile("cp.async.wait_group 0;");
        }
        __syncthreads();

        // this warp handles quads wid*4 .. wid*4+3 of the chunk
        #pragma unroll
        for (int qq = 0; qq < 4; qq++) {
            const int q    = wid * 4 + qq;
            const int xcol = (q ^ tt) * 4;      // de-swizzle (row>>3 == tt)
            const int wcol = (q ^ et) * 4;      // de-swizzle (row>>3 == et)

            ulonglong2 wq[8];
            #pragma unroll
            for (int j = 0; j < 8; j++)
                wq[j] = *(const ulonglong2*)&sm[b][64 + et * 8 + j][wcol];

            #pragma unroll
            for (int i = 0; i < 8; i++) {
                ulonglong2 xq = *(const ulonglong2*)&sm[b][tt * 8 + i][xcol];
                #pragma unroll
                for (int j = 0; j < 8; j++) {
                    fma2(acc[i][j], xq.x, wq[j].x);
                    fma2(acc[i][j], xq.y, wq[j].y);
                }
            }
        }
        __syncthreads();
    }

    // ---- cross-warp partial reduce via smem overlay part[4][64][40] ----
    float* part = &sm[0][0][0];   // 10240 floats < 12288 available
    #pragma unroll
    for (int i = 0; i < 8; i++) {
        int tok = tt * 8 + i;
        #pragma unroll
        for (int k = 0; k < 2; k++) {
            int q = et * 2 + k;                 // 8B-quad of the 32-expert row
            float4 v;
            v.x = accsum(acc[i][4 * k + 0]);
            v.y = accsum(acc[i][4 * k + 1]);
            v.z = accsum(acc[i][4 * k + 2]);
            v.w = accsum(acc[i][4 * k + 3]);
            int sq = q ^ tt;                    // swizzle by tok>>3 == tt
            *(float4*)&part[((wid * 64 + tok) * 40) + sq * 4] = v;
        }
    }
    __syncthreads();

    // ---- reduce 4 partials + bias, segmented (8-lane) top-4 + softmax ----
    #pragma unroll
    for (int p = 0; p < 4; p++) {
        int tok = p * 16 + (tid >> 3);          // 16 tokens per pass
        int ls  = tid & 7;                      // lane-in-segment: experts ls*4..ls*4+3
        int sq  = ls ^ ((tok >> 3) & 7);

        float4 s = *(float4*)&part[((0 * 64 + tok) * 40) + sq * 4];
        #pragma unroll
        for (int w = 1; w < 4; w++) {
            float4 a = *(float4*)&part[((w * 64 + tok) * 40) + sq * 4];
            s.x += a.x; s.y += a.y; s.z += a.z; s.w += a.w;
        }
        float4 bb = *(const float4*)&bias[ls * 4];
        float vv[4] = { s.x + bb.x, s.y + bb.y, s.z + bb.z, s.w + bb.w };

        float vals[TOPK]; int idxs[TOPK];
        #pragma unroll
        for (int k = 0; k < TOPK; k++) {
            float mv = vv[0]; int mn = 0;
            #pragma unroll
            for (int n = 1; n < 4; n++)
                if (vv[n] > mv) { mv = vv[n]; mn = n; }   // ties -> lowest n
            int mi = ls * 4 + mn;
            #pragma unroll
            for (int off = 4; off > 0; off >>= 1) {
                float ov = __shfl_xor_sync(0xffffffffu, mv, off, 8);
                int   oi = __shfl_xor_sync(0xffffffffu, mi, off, 8);
                if (ov > mv || (ov == mv && oi < mi)) { mv = ov; mi = oi; }
            }
            vals[k] = mv; idxs[k] = mi;
            if ((mi >> 2) == ls) vv[mi & 3] = -3.4e38f;   // remove winner
        }

        if (ls == 0) {
            float e0 = 1.0f;
            float e1 = __expf(vals[1] - vals[0]);
            float e2 = __expf(vals[2] - vals[0]);
            float e3 = __expf(vals[3] - vals[0]);
            float inv = 1.0f / (e0 + e1 + e2 + e3);
            size_t base = (size_t)(t0 + tok) * TOPK;
            *(float4*)&out[base] = make_float4((float)idxs[0], (float)idxs[1],
                                               (float)idxs[2], (float)idxs[3]);
            *(float4*)&out[(size_t)T * TOPK + base] =
                make_float4(e0 * inv, e1 * inv, e2 * inv, e3 * inv);
        }
    }
}

extern "C" void kernel_launch(void* const* d_in, const int* in_sizes, int n_in,
                              void* d_out, int out_size) {
    const float* X    = (const float*)d_in[0];
    const float* W    = (const float*)d_in[1];
    const float* bias = (const float*)d_in[2];
    int T = in_sizes[0] / HDIM;          // 16384
    int blocks = T / TOK_TILE;           // 256
    gate_kernel<<<blocks, NTHREADS>>>(X, W, bias, (float*)d_out, T);
}